// round 4
// baseline (speedup 1.0000x reference)
#include <cuda_runtime.h>

#define MAXN 50000
#define MAXE 800000
#define NSEG (MAXN * 8)

// ---------------- scratch (static device globals; no allocation) ----------------
__device__ float g_U[(size_t)MAXN * 256];
__device__ float g_h[(size_t)MAXN * 128];
__device__ float g_as[MAXN * 2];
__device__ float g_ad[MAXN * 2];
__device__ float g_x1a[(size_t)MAXN * 64];
__device__ float g_x1b[(size_t)MAXN * 64];
__device__ float g_x2a[(size_t)MAXN * 64];
__device__ float g_x2b[(size_t)MAXN * 64];
__device__ float g_r2[MAXN * 16];
__device__ float g_g2[MAXN * 16];
__device__ int g_cnt8[NSEG];
__device__ int g_off8[NSEG + 1];
__device__ int g_cur8[NSEG];
__device__ int g_csrc[MAXE];

__device__ __forceinline__ float lrelu(float v) { return v > 0.f ? v : 0.2f * v; }

// ---------------- CSR build over seg = dst*8 + etype ----------------
__global__ void k_hist(const int* __restrict__ dst, const int* __restrict__ et, int E,
                       int* __restrict__ cnt) {
    int i = blockIdx.x * blockDim.x + threadIdx.x;
    if (i < E) atomicAdd(&cnt[dst[i] * 8 + et[i]], 1);
}

__global__ void k_scan(const int* __restrict__ cnt, int* __restrict__ off,
                       int* __restrict__ cur, int n) {
    __shared__ int tot[1024];
    int tid = threadIdx.x;
    int chunk = (n + 1023) >> 10;
    int s = tid * chunk;
    int e = min(s + chunk, n);
    int sum = 0;
    for (int i = s; i < e; i++) sum += cnt[i];
    tot[tid] = sum;
    __syncthreads();
    if (tid == 0) {
        int acc = 0;
        for (int i = 0; i < 1024; i++) { int t = tot[i]; tot[i] = acc; acc += t; }
    }
    __syncthreads();
    int acc = tot[tid];
    for (int i = s; i < e; i++) {
        off[i] = acc;
        cur[i] = acc;
        acc += cnt[i];
    }
    if (s < n && e == n) off[n] = acc;
}

__global__ void k_scatter(const int* __restrict__ src, const int* __restrict__ dst,
                          const int* __restrict__ et, int E, int* __restrict__ cur,
                          int* __restrict__ csrc) {
    int i = blockIdx.x * blockDim.x + threadIdx.x;
    if (i < E) {
        int p = atomicAdd(&cur[dst[i] * 8 + et[i]], 1);
        csrc[p] = src[i];
    }
}

// ---------------- RGCN aggregation (warp per node, all-register) ----------------
// U[n, b*64+c] = sum_r comp[r,b] * (sum_{e in seg(n,r)} x[src[e]][c]) / max(cnt,1)
__global__ __launch_bounds__(256) void k_rgcn_agg(
        const float* __restrict__ x, const int* __restrict__ off8,
        const int* __restrict__ csrc, const float* __restrict__ comp,
        float* __restrict__ U, int n) {
    int w = threadIdx.x >> 5, lane = threadIdx.x & 31;
    int node = blockIdx.x * 8 + w;
    if (node >= n) return;
    float2 bacc[4];
#pragma unroll
    for (int b = 0; b < 4; b++) bacc[b] = make_float2(0.f, 0.f);
    const int* o = off8 + node * 8;
#pragma unroll 1
    for (int r = 0; r < 8; r++) {
        int s0 = o[r], e0 = o[r + 1];
        if (s0 == e0) continue;
        float2 sum = {0.f, 0.f};
        int s = csrc[s0];
        float2 v = *(const float2*)(x + (size_t)s * 64 + 2 * lane);
        for (int e = s0; e < e0; e++) {
            int e2 = (e + 1 < e0) ? e + 1 : e;
            int s2 = csrc[e2];
            float2 v2 = *(const float2*)(x + (size_t)s2 * 64 + 2 * lane);
            sum.x += v.x;
            sum.y += v.y;
            v = v2;
        }
        float invc = 1.f / (float)(e0 - s0);
#pragma unroll
        for (int b = 0; b < 4; b++) {
            float f = comp[r * 4 + b] * invc;
            bacc[b].x += f * sum.x;
            bacc[b].y += f * sum.y;
        }
    }
#pragma unroll
    for (int b = 0; b < 4; b++)
        ((float2*)(U + (size_t)node * 256 + b * 64))[lane] = bacc[b];
}

// ---------------- generic tiled GEMM: C = [A1|A2] @ [B1;B2] (+bias)(+relu) ----------------
// K1 and K2 must be multiples of BK (holds for all uses: 256/64, 64/0).
template <int BN, int TN>
__global__ __launch_bounds__(256) void k_gemm(const float* __restrict__ A1, int K1,
                                              const float* __restrict__ A2, int K2,
                                              const float* __restrict__ B1,
                                              const float* __restrict__ B2,
                                              const float* __restrict__ bias,
                                              float* __restrict__ C, int n, int do_relu) {
    constexpr int BM = 128, BK = 32, TM = 8;
    static_assert(BN / TN == 16, "");
    __shared__ float As[BM][BK + 1];
    __shared__ float Bs[BK][BN];
    int tid = threadIdx.x;
    int tx = tid & 15, ty = tid >> 4;
    int row0 = blockIdx.x * BM;
    int K = K1 + K2;
    float acc[TM][TN];
#pragma unroll
    for (int i = 0; i < TM; i++)
#pragma unroll
        for (int j = 0; j < TN; j++) acc[i][j] = 0.f;

    for (int kt = 0; kt < K; kt += BK) {
        const float* Ab;
        int Ast, kcol;
        const float* Bb;
        if (kt < K1) { Ab = A1; Ast = K1; kcol = kt; Bb = B1 + (size_t)kt * BN; }
        else { Ab = A2; Ast = K2; kcol = kt - K1; Bb = B2 + (size_t)(kt - K1) * BN; }
#pragma unroll
        for (int i = 0; i < (BM * BK) / 256; i++) {
            int idx = tid + i * 256;
            int r = idx >> 5, k = idx & 31;
            int row = row0 + r;
            As[r][k] = (row < n) ? Ab[(size_t)row * Ast + kcol + k] : 0.f;
        }
#pragma unroll
        for (int i = 0; i < (BK * BN) / 256; i++) {
            int idx = tid + i * 256;
            int r = idx / BN, c = idx % BN;
            Bs[r][c] = Bb[r * BN + c];
        }
        __syncthreads();
#pragma unroll
        for (int kk = 0; kk < BK; kk++) {
            float a[TM], b[TN];
#pragma unroll
            for (int i = 0; i < TM; i++) a[i] = As[ty * TM + i][kk];
#pragma unroll
            for (int j = 0; j < TN; j++) b[j] = Bs[kk][tx * TN + j];
#pragma unroll
            for (int i = 0; i < TM; i++)
#pragma unroll
                for (int j = 0; j < TN; j++) acc[i][j] += a[i] * b[j];
        }
        __syncthreads();
    }
#pragma unroll
    for (int i = 0; i < TM; i++) {
        int row = row0 + ty * TM + i;
        if (row >= n) continue;
#pragma unroll
        for (int j = 0; j < TN; j++) {
            int c = tx * TN + j;
            float v = acc[i][j];
            if (bias) v += bias[c];
            if (do_relu) v = fmaxf(v, 0.f);
            C[(size_t)row * BN + c] = v;
        }
    }
}

// ---------------- GAT attention coefficients (warp per node) ----------------
template <int C>
__global__ __launch_bounds__(256) void k_attcoef(
        const float* __restrict__ h, const float* __restrict__ att_s,
        const float* __restrict__ att_d, float* __restrict__ as_,
        float* __restrict__ ad_, int n) {
    int w = threadIdx.x >> 5, lane = threadIdx.x & 31;
    int node = blockIdx.x * (blockDim.x >> 5) + w;
    if (node >= n) return;
    const float* hn = h + (size_t)node * 2 * C;
    if (C >= 32) {
        float s0 = 0, s1 = 0, d0 = 0, d1 = 0;
#pragma unroll
        for (int j = 0; j < C / 32; j++) {
            int c = lane + 32 * j;
            float h0 = hn[c], h1 = hn[C + c];
            s0 += h0 * att_s[c];
            s1 += h1 * att_s[C + c];
            d0 += h0 * att_d[c];
            d1 += h1 * att_d[C + c];
        }
#pragma unroll
        for (int o = 16; o; o >>= 1) {
            s0 += __shfl_xor_sync(0xffffffffu, s0, o);
            s1 += __shfl_xor_sync(0xffffffffu, s1, o);
            d0 += __shfl_xor_sync(0xffffffffu, d0, o);
            d1 += __shfl_xor_sync(0xffffffffu, d1, o);
        }
        if (lane == 0) {
            as_[node * 2] = s0;
            as_[node * 2 + 1] = s1;
            ad_[node * 2] = d0;
            ad_[node * 2 + 1] = d1;
        }
    } else {  // C == 16
        float hv = hn[lane];
        float s = hv * att_s[lane];
        float d = hv * att_d[lane];
#pragma unroll
        for (int o = 8; o; o >>= 1) {
            s += __shfl_xor_sync(0xffffffffu, s, o);
            d += __shfl_xor_sync(0xffffffffu, d, o);
        }
        if (lane == 0) { as_[node * 2] = s; ad_[node * 2] = d; }
        if (lane == 16) { as_[node * 2 + 1] = s; ad_[node * 2 + 1] = d; }
    }
}

// ---------------- GAT aggregation, C=64 (warp per node, float4 + pipeline) ----------------
__global__ __launch_bounds__(256) void k_gat_agg64(
        const float* __restrict__ h, const float* __restrict__ as_,
        const float* __restrict__ ad_, const int* __restrict__ off8,
        const int* __restrict__ csrc, const float* __restrict__ bias,
        float* __restrict__ out, int n, int do_relu) {
    int w = threadIdx.x >> 5, lane = threadIdx.x & 31;
    int node = blockIdx.x * (blockDim.x >> 5) + w;
    if (node >= n) return;
    float2 adv = ((const float2*)ad_)[node];
    float2 asn = ((const float2*)as_)[node];
    int st = off8[node * 8], en = off8[node * 8 + 8];
    // pass 1: per-head max (self loop included), lane-parallel
    float m0 = lrelu(asn.x + adv.x);
    float m1 = lrelu(asn.y + adv.y);
    for (int i = st + lane; i < en; i += 32) {
        float2 av = ((const float2*)as_)[csrc[i]];
        m0 = fmaxf(m0, lrelu(av.x + adv.x));
        m1 = fmaxf(m1, lrelu(av.y + adv.y));
    }
#pragma unroll
    for (int o = 16; o; o >>= 1) {
        m0 = fmaxf(m0, __shfl_xor_sync(0xffffffffu, m0, o));
        m1 = fmaxf(m1, __shfl_xor_sync(0xffffffffu, m1, o));
    }
    // pass 2: softmax-weighted accumulation, float4 gather, 1-deep pipeline
    float4 acc = {0.f, 0.f, 0.f, 0.f};
    float sum0 = 0.f, sum1 = 0.f;
    int s = (st < en) ? csrc[st] : node;
    float4 v = ((const float4*)(h + (size_t)s * 128))[lane];
    float2 av = ((const float2*)as_)[s];
    for (int e = st; e <= en; e++) {
        int s2 = (e + 1 < en) ? csrc[e + 1] : node;
        float4 v2 = ((const float4*)(h + (size_t)s2 * 128))[lane];
        float2 av2 = ((const float2*)as_)[s2];
        float w0 = __expf(lrelu(av.x + adv.x) - m0);
        float w1 = __expf(lrelu(av.y + adv.y) - m1);
        sum0 += w0;
        sum1 += w1;
        float ww = (lane < 16) ? w0 : w1;
        acc.x += ww * v.x;
        acc.y += ww * v.y;
        acc.z += ww * v.z;
        acc.w += ww * v.w;
        s = s2; v = v2; av = av2;
    }
    float rn = (lane < 16) ? (1.f / sum0) : (1.f / sum1);
    acc.x *= rn; acc.y *= rn; acc.z *= rn; acc.w *= rn;
    float4 other;
    other.x = __shfl_xor_sync(0xffffffffu, acc.x, 16);
    other.y = __shfl_xor_sync(0xffffffffu, acc.y, 16);
    other.z = __shfl_xor_sync(0xffffffffu, acc.z, 16);
    other.w = __shfl_xor_sync(0xffffffffu, acc.w, 16);
    if (lane < 16) {
        float4 b4 = ((const float4*)bias)[lane];
        float4 o;
        o.x = 0.5f * (acc.x + other.x) + b4.x;
        o.y = 0.5f * (acc.y + other.y) + b4.y;
        o.z = 0.5f * (acc.z + other.z) + b4.z;
        o.w = 0.5f * (acc.w + other.w) + b4.w;
        if (do_relu) {
            o.x = fmaxf(o.x, 0.f); o.y = fmaxf(o.y, 0.f);
            o.z = fmaxf(o.z, 0.f); o.w = fmaxf(o.w, 0.f);
        }
        ((float4*)(out + (size_t)node * 64))[lane] = o;
    }
}

// ---------------- GAT aggregation, C=16 (warp per node) ----------------
__global__ __launch_bounds__(256) void k_gat_agg16(
        const float* __restrict__ h, const float* __restrict__ as_,
        const float* __restrict__ ad_, const int* __restrict__ off8,
        const int* __restrict__ csrc, const float* __restrict__ bias,
        float* __restrict__ out, int n) {
    int w = threadIdx.x >> 5, lane = threadIdx.x & 31;
    int node = blockIdx.x * (blockDim.x >> 5) + w;
    if (node >= n) return;
    float2 adv = ((const float2*)ad_)[node];
    float2 asn = ((const float2*)as_)[node];
    int st = off8[node * 8], en = off8[node * 8 + 8];
    float m0 = lrelu(asn.x + adv.x);
    float m1 = lrelu(asn.y + adv.y);
    for (int i = st + lane; i < en; i += 32) {
        float2 av = ((const float2*)as_)[csrc[i]];
        m0 = fmaxf(m0, lrelu(av.x + adv.x));
        m1 = fmaxf(m1, lrelu(av.y + adv.y));
    }
#pragma unroll
    for (int o = 16; o; o >>= 1) {
        m0 = fmaxf(m0, __shfl_xor_sync(0xffffffffu, m0, o));
        m1 = fmaxf(m1, __shfl_xor_sync(0xffffffffu, m1, o));
    }
    float acc = 0.f, sum0 = 0.f, sum1 = 0.f;
    for (int e = st; e <= en; e++) {
        int s = (e < en) ? csrc[e] : node;
        float2 av = ((const float2*)as_)[s];
        float w0 = __expf(lrelu(av.x + adv.x) - m0);
        float w1 = __expf(lrelu(av.y + adv.y) - m1);
        sum0 += w0;
        sum1 += w1;
        acc += ((lane < 16) ? w0 : w1) * h[(size_t)s * 32 + lane];
    }
    float r0 = 1.f / sum0, r1 = 1.f / sum1;
    float other = __shfl_xor_sync(0xffffffffu, acc, 16);
    if (lane < 16) {
        out[(size_t)node * 16 + lane] = 0.5f * (acc * r0 + other * r1) + bias[lane];
    }
}

// ---------------- final combine: tanh(r2 + rowmean(g2)) ----------------
__global__ void k_combine(const float* __restrict__ r2, const float* __restrict__ g2,
                          float* __restrict__ out, int n) {
    int t = blockIdx.x * blockDim.x + threadIdx.x;
    int node = t >> 4, c = t & 15;
    if (node >= n) return;
    float gv = g2[node * 16 + c];
    float s = gv;
#pragma unroll
    for (int o = 8; o; o >>= 1) s += __shfl_xor_sync(0xffffffffu, s, o);
    out[node * 16 + c] = tanhf(r2[node * 16 + c] + s * (1.f / 16.f));
}

// ---------------- host orchestration ----------------
extern "C" void kernel_launch(void* const* d_in, const int* in_sizes, int n_in,
                              void* d_out, int out_size) {
    const float* x = (const float*)d_in[0];
    const int* ei = (const int*)d_in[1];
    const int* et = (const int*)d_in[2];
    int E = in_sizes[2];
    int N = in_sizes[0] / 64;
    if (N > MAXN) N = MAXN;
    if (E > MAXE) E = MAXE;
    const int* src = ei;
    const int* dst = ei + E;

    const float *rb[3], *rc[3], *rr[3], *rbias[3], *gw[3], *gas[3], *gad[3], *gb[3];
    for (int k = 0; k < 3; k++) {
        int base = 3 + 8 * k;
        rb[k] = (const float*)d_in[base + 0];
        rc[k] = (const float*)d_in[base + 1];
        rr[k] = (const float*)d_in[base + 2];
        rbias[k] = (const float*)d_in[base + 3];
        gw[k] = (const float*)d_in[base + 4];
        gas[k] = (const float*)d_in[base + 5];
        gad[k] = (const float*)d_in[base + 6];
        gb[k] = (const float*)d_in[base + 7];
    }

    void* p;
    float *U, *h, *as_, *ad_, *x1a, *x1b, *x2a, *x2b, *r2, *g2;
    int *cnt8, *off8, *cur8, *csrc;
    cudaGetSymbolAddress(&p, g_U);   U = (float*)p;
    cudaGetSymbolAddress(&p, g_h);   h = (float*)p;
    cudaGetSymbolAddress(&p, g_as);  as_ = (float*)p;
    cudaGetSymbolAddress(&p, g_ad);  ad_ = (float*)p;
    cudaGetSymbolAddress(&p, g_x1a); x1a = (float*)p;
    cudaGetSymbolAddress(&p, g_x1b); x1b = (float*)p;
    cudaGetSymbolAddress(&p, g_x2a); x2a = (float*)p;
    cudaGetSymbolAddress(&p, g_x2b); x2b = (float*)p;
    cudaGetSymbolAddress(&p, g_r2);  r2 = (float*)p;
    cudaGetSymbolAddress(&p, g_g2);  g2 = (float*)p;
    cudaGetSymbolAddress(&p, g_cnt8); cnt8 = (int*)p;
    cudaGetSymbolAddress(&p, g_off8); off8 = (int*)p;
    cudaGetSymbolAddress(&p, g_cur8); cur8 = (int*)p;
    cudaGetSymbolAddress(&p, g_csrc); csrc = (int*)p;

    // CSR build over seg = dst*8 + etype
    cudaMemsetAsync(cnt8, 0, (size_t)N * 8 * sizeof(int), 0);
    k_hist<<<(E + 255) / 256, 256>>>(dst, et, E, cnt8);
    k_scan<<<1, 1024>>>(cnt8, off8, cur8, N * 8);
    k_scatter<<<(E + 255) / 256, 256>>>(src, dst, et, E, cur8, csrc);

    int gWarp = (N + 7) / 8;      // warp-per-node kernels, 256 threads
    int gGemm = (N + 127) / 128;  // BM=128

    // ---- layer 0 ----
    k_rgcn_agg<<<gWarp, 256>>>(x, off8, csrc, rc[0], U, N);
    k_gemm<64, 4><<<gGemm, 256>>>(U, 256, x, 64, rb[0], rr[0], rbias[0], x1a, N, 1);

    k_gemm<128, 8><<<gGemm, 256>>>(x, 64, nullptr, 0, gw[0], nullptr, nullptr, h, N, 0);
    k_attcoef<64><<<gWarp, 256>>>(h, gas[0], gad[0], as_, ad_, N);
    k_gat_agg64<<<gWarp, 256>>>(h, as_, ad_, off8, csrc, gb[0], x2a, N, 1);

    // ---- layer 1 ----
    k_rgcn_agg<<<gWarp, 256>>>(x1a, off8, csrc, rc[1], U, N);
    k_gemm<64, 4><<<gGemm, 256>>>(U, 256, x1a, 64, rb[1], rr[1], rbias[1], x1b, N, 1);

    k_gemm<128, 8><<<gGemm, 256>>>(x2a, 64, nullptr, 0, gw[1], nullptr, nullptr, h, N, 0);
    k_attcoef<64><<<gWarp, 256>>>(h, gas[1], gad[1], as_, ad_, N);
    k_gat_agg64<<<gWarp, 256>>>(h, as_, ad_, off8, csrc, gb[1], x2b, N, 1);

    // ---- swap: layer 2 RGCN consumes GAT branch (x2b), GAT consumes RGCN branch (x1b) ----
    k_rgcn_agg<<<gWarp, 256>>>(x2b, off8, csrc, rc[2], U, N);
    k_gemm<16, 1><<<gGemm, 256>>>(U, 256, x2b, 64, rb[2], rr[2], rbias[2], r2, N, 0);

    k_gemm<32, 2><<<gGemm, 256>>>(x1b, 64, nullptr, 0, gw[2], nullptr, nullptr, h, N, 0);
    k_attcoef<16><<<gWarp, 256>>>(h, gas[2], gad[2], as_, ad_, N);
    k_gat_agg16<<<gWarp, 256>>>(h, as_, ad_, off8, csrc, gb[2], g2, N);

    // ---- combine ----
    k_combine<<<(N * 16 + 255) / 256, 256>>>(r2, g2, (float*)d_out, N);
}